// round 1
// baseline (speedup 1.0000x reference)
#include <cuda_runtime.h>
#include <cuda_bf16.h>

// Problem shapes (compile-time constants)
#define VOCAB   32000
#define EMB_DIM 1024
#define CTX     2048
#define BATCH   2
#define ROWS    (BATCH * CTX)          // 4096
#define VEC4    (VOCAB / 4)            // 8000 float4 per row

// One block per (b, t) row.
// Phase 1: find the one-hot index by scanning the 32000-float row with float4
//          loads; early-exit via a volatile shared flag once found.
// Phase 2: out[row] = W[idx] + pos[t]  (256 x float4).
__global__ __launch_bounds__(256) void embed_gather_kernel(
    const float* __restrict__ X,     // (ROWS, VOCAB)
    const float* __restrict__ W,     // (VOCAB, EMB_DIM)
    const float* __restrict__ pos,   // (CTX, EMB_DIM)
    float* __restrict__ out)         // (ROWS, EMB_DIM)
{
    const int row = blockIdx.x;            // 0..4095
    const int t   = row & (CTX - 1);       // position within context
    const int tid = threadIdx.x;

    __shared__ int s_idx;
    if (tid == 0) s_idx = -1;
    __syncthreads();

    volatile int* vflag = &s_idx;

    const float4* __restrict__ xr =
        reinterpret_cast<const float4*>(X + (size_t)row * VOCAB);

    // Strided scan: iteration i covers a contiguous 1024-float chunk of the row,
    // so expected iterations until the hot element is loaded ~= idx/1024.
    // The flag check costs one shared read per iteration; a stale read costs at
    // most one extra iteration of (harmless) loads.
    for (int i = tid; i < VEC4; i += 256) {
        float4 v = xr[i];
        if (v.x != 0.0f || v.y != 0.0f || v.z != 0.0f || v.w != 0.0f) {
            int off = (v.x != 0.0f) ? 0 : (v.y != 0.0f) ? 1 : (v.z != 0.0f) ? 2 : 3;
            s_idx = i * 4 + off;   // exactly one thread in the block ever writes
        }
        if (*vflag >= 0) break;
    }
    __syncthreads();               // all threads see the final s_idx

    const int idx = s_idx;

    // Phase 2: 1024 floats = 256 float4 -> one per thread.
    const float4* __restrict__ wr =
        reinterpret_cast<const float4*>(W + (size_t)idx * EMB_DIM);
    const float4* __restrict__ pr =
        reinterpret_cast<const float4*>(pos + (size_t)t * EMB_DIM);
    float4* __restrict__ orow =
        reinterpret_cast<float4*>(out + (size_t)row * EMB_DIM);

    float4 w4 = wr[tid];
    float4 p4 = pr[tid];
    float4 o4;
    o4.x = w4.x + p4.x;
    o4.y = w4.y + p4.y;
    o4.z = w4.z + p4.z;
    o4.w = w4.w + p4.w;
    orow[tid] = o4;
}

extern "C" void kernel_launch(void* const* d_in, const int* in_sizes, int n_in,
                              void* d_out, int out_size)
{
    const float* X   = (const float*)d_in[0];   // (2, 2048, 32000)
    const float* W   = (const float*)d_in[1];   // (32000, 1024)
    const float* pos = (const float*)d_in[2];   // (2048, 1024)
    float* out       = (float*)d_out;           // (2, 2048, 1024)

    embed_gather_kernel<<<ROWS, 256>>>(X, W, pos, out);
}

// round 3
// speedup vs baseline: 1.1831x; 1.1831x over previous
#include <cuda_runtime.h>
#include <cuda_bf16.h>

// Problem shapes
#define VOCAB   32000
#define EMB_DIM 1024
#define CTX     2048
#define BATCH   2
#define ROWS    (BATCH * CTX)          // 4096
#define VEC4    (VOCAB / 4)            // 8000 float4 per row
#define UNROLL  4                      // float4 loads in flight per thread per flag check
#define STEP    (256 * UNROLL)         // 1024 float4 = 16 KB per outer iteration
#define FULL    ((VEC4 / STEP) * STEP) // 7168: last full-chunk boundary

// One block per (b, t) row.
// Phase 1: find the one-hot index. 4-deep unrolled float4 scan (MLP=4) with a
//          shared early-exit flag checked once per 16 KB chunk. Tail peeled so
//          the hot loop has unconditional loads.
// Phase 2: out[row] = W[idx] + pos[t]  (256 x float4).
__global__ __launch_bounds__(256) void embed_gather_kernel(
    const float* __restrict__ X,     // (ROWS, VOCAB)
    const float* __restrict__ W,     // (VOCAB, EMB_DIM)
    const float* __restrict__ pos,   // (CTX, EMB_DIM)
    float* __restrict__ out)         // (ROWS, EMB_DIM)
{
    const int row = blockIdx.x;            // 0..4095
    const int t   = row & (CTX - 1);       // position within context
    const int tid = threadIdx.x;

    __shared__ int s_idx;
    if (tid == 0) s_idx = -1;
    __syncthreads();

    volatile int* vflag = &s_idx;

    const float4* __restrict__ xr =
        reinterpret_cast<const float4*>(X + (size_t)row * VOCAB);

    // Main loop: 7 full 16 KB chunks, unconditional loads (MLP=4 per thread).
    for (int base = 0; base < FULL; base += STEP) {
        float4 v[UNROLL];
        #pragma unroll
        for (int k = 0; k < UNROLL; k++)
            v[k] = __ldcs(&xr[base + tid + k * 256]);   // streaming: X is dead after read
        #pragma unroll
        for (int k = 0; k < UNROLL; k++) {
            if (v[k].x != 0.0f || v[k].y != 0.0f || v[k].z != 0.0f || v[k].w != 0.0f) {
                int off = (v[k].x != 0.0f) ? 0 : (v[k].y != 0.0f) ? 1
                        : (v[k].z != 0.0f) ? 2 : 3;
                s_idx = (base + tid + k * 256) * 4 + off;  // unique writer
            }
        }
        if (*vflag >= 0) break;
    }

    // Peeled tail: 832 float4 (indices FULL..VEC4), predicated, only reached if
    // the index lives in the last partial chunk.
    if (*vflag < 0) {
        #pragma unroll
        for (int k = 0; k < UNROLL; k++) {
            int i = FULL + tid + k * 256;
            if (i < VEC4) {
                float4 v = __ldcs(&xr[i]);
                if (v.x != 0.0f || v.y != 0.0f || v.z != 0.0f || v.w != 0.0f) {
                    int off = (v.x != 0.0f) ? 0 : (v.y != 0.0f) ? 1
                            : (v.z != 0.0f) ? 2 : 3;
                    s_idx = i * 4 + off;
                }
            }
        }
    }
    __syncthreads();               // all threads see the final s_idx

    const int idx = s_idx;

    // Phase 2: 1024 floats = 256 float4 -> one per thread.
    const float4* __restrict__ wr =
        reinterpret_cast<const float4*>(W + (size_t)idx * EMB_DIM);
    const float4* __restrict__ pr =
        reinterpret_cast<const float4*>(pos + (size_t)t * EMB_DIM);
    float4* __restrict__ orow =
        reinterpret_cast<float4*>(out + (size_t)row * EMB_DIM);

    float4 w4 = wr[tid];
    float4 p4 = pr[tid];
    float4 o4;
    o4.x = w4.x + p4.x;
    o4.y = w4.y + p4.y;
    o4.z = w4.z + p4.z;
    o4.w = w4.w + p4.w;
    orow[tid] = o4;
}

extern "C" void kernel_launch(void* const* d_in, const int* in_sizes, int n_in,
                              void* d_out, int out_size)
{
    const float* X   = (const float*)d_in[0];   // (2, 2048, 32000)
    const float* W   = (const float*)d_in[1];   // (32000, 1024)
    const float* pos = (const float*)d_in[2];   // (2048, 1024)
    float* out       = (float*)d_out;           // (2, 2048, 1024)

    embed_gather_kernel<<<ROWS, 256>>>(X, W, pos, out);
}